// round 1
// baseline (speedup 1.0000x reference)
#include <cuda_runtime.h>
#include <math.h>

#define Bsz 4
#define AT 128
#define NBR 20
#define NK 19
#define R2 (Bsz*AT*NBR)        // 10240 edge rows
#define NODES (Bsz*AT)         // 512
#define CNT3 (R2*NK)           // 194560 three-body rows

// ---------------- scratch (static device globals; no allocation) ----------------
__device__ float d_C2[R2*128];        // masked node_i*node_j products
__device__ float d_Y2[R2*256];        // two-body pre-BN GEMM output
__device__ float d_PN[NODES*768];     // node @ [W3a|W3b|W3c]
__device__ float d_QE[R2*512];        // edge @ [W3d|W3e]
__device__ float d_TB[R2*128];        // three-body pre-final-BN sums
__device__ float d_psum[640*256];
__device__ float d_psq [640*256];
__device__ float d_scale2[256], d_shift2[256];
__device__ float d_scale3[256], d_shift3[256];
__device__ float d_scaleS[128], d_shiftS[128];

__device__ __forceinline__ float sigmoidf_(float x) { return 1.f/(1.f + __expf(-x)); }

// ---------------- c2 = node_i * node_j * mask ----------------
__global__ void k_c2(const float* __restrict__ node, const int* __restrict__ nbr_idx,
                     const int* __restrict__ nbr_mask) {
    int idx = blockIdx.x*256 + threadIdx.x;
    if (idx >= R2*128) return;
    int f = idx & 127, r = idx >> 7;
    int j = nbr_idx[r];
    int b = r / (AT*NBR);
    float m = (float)nbr_mask[r];
    d_C2[idx] = node[(r/NBR)*128 + f] * node[(b*AT + j)*128 + f] * m;
}

// ---------------- generic fp32 GEMM: C[M,N] = A[M,128] @ B[128,N] ----------------
// grid: (N/64, M/64), 256 threads, 64x64 tile, 4x4 per thread
__global__ void __launch_bounds__(256) gemm_k128(
    const float* __restrict__ A, const float* __restrict__ B,
    float* __restrict__ C, int ldb, int ldc) {
    __shared__ float Ast[64][65];   // transposed: Ast[k][m]
    __shared__ float Bs[64][64];
    int tid = threadIdx.x;
    int txx = tid & 15, tym = tid >> 4;
    int m0 = blockIdx.y * 64, n0 = blockIdx.x * 64;
    float acc[4][4] = {};
    for (int k0 = 0; k0 < 128; k0 += 64) {
        #pragma unroll
        for (int l = 0; l < 16; l++) {
            int e = l*256 + tid;
            int m = e >> 6, k = e & 63;
            Ast[k][m] = A[(m0+m)*128 + k0 + k];
        }
        #pragma unroll
        for (int l = 0; l < 16; l++) {
            int e = l*256 + tid;
            int k = e >> 6, n = e & 63;
            Bs[k][n] = B[(k0+k)*ldb + n0 + n];
        }
        __syncthreads();
        #pragma unroll 8
        for (int kk = 0; kk < 64; kk++) {
            float a0 = Ast[kk][tym*4+0];
            float a1 = Ast[kk][tym*4+1];
            float a2 = Ast[kk][tym*4+2];
            float a3 = Ast[kk][tym*4+3];
            float4 bv = *(const float4*)&Bs[kk][txx*4];
            acc[0][0] = fmaf(a0, bv.x, acc[0][0]); acc[0][1] = fmaf(a0, bv.y, acc[0][1]);
            acc[0][2] = fmaf(a0, bv.z, acc[0][2]); acc[0][3] = fmaf(a0, bv.w, acc[0][3]);
            acc[1][0] = fmaf(a1, bv.x, acc[1][0]); acc[1][1] = fmaf(a1, bv.y, acc[1][1]);
            acc[1][2] = fmaf(a1, bv.z, acc[1][2]); acc[1][3] = fmaf(a1, bv.w, acc[1][3]);
            acc[2][0] = fmaf(a2, bv.x, acc[2][0]); acc[2][1] = fmaf(a2, bv.y, acc[2][1]);
            acc[2][2] = fmaf(a2, bv.z, acc[2][2]); acc[2][3] = fmaf(a2, bv.w, acc[2][3]);
            acc[3][0] = fmaf(a3, bv.x, acc[3][0]); acc[3][1] = fmaf(a3, bv.y, acc[3][1]);
            acc[3][2] = fmaf(a3, bv.z, acc[3][2]); acc[3][3] = fmaf(a3, bv.w, acc[3][3]);
        }
        __syncthreads();
    }
    #pragma unroll
    for (int i = 0; i < 4; i++)
        #pragma unroll
        for (int jj = 0; jj < 4; jj++)
            C[(m0 + tym*4 + i)*ldc + n0 + txx*4 + jj] = acc[i][jj];
}

// ---------------- BN stat partials ----------------
__global__ void k_stats_part256(const float* __restrict__ X, int rowsPerBlk) {
    int c = threadIdx.x;
    float s = 0.f, q = 0.f;
    int r0 = blockIdx.x * rowsPerBlk;
    for (int i = 0; i < rowsPerBlk; i++) {
        float v = X[(r0+i)*256 + c];
        s += v; q = fmaf(v, v, q);
    }
    d_psum[blockIdx.x*256 + c] = s;
    d_psq [blockIdx.x*256 + c] = q;
}

__global__ void k_stats_part128(const float* __restrict__ X, int rowsPerBlk) {
    int c = threadIdx.x;
    float s = 0.f, q = 0.f;
    int r0 = blockIdx.x * rowsPerBlk;
    for (int i = 0; i < rowsPerBlk; i++) {
        float v = X[(r0+i)*128 + c];
        s += v; q = fmaf(v, v, q);
    }
    d_psum[blockIdx.x*128 + c] = s;
    d_psq [blockIdx.x*128 + c] = q;
}

// finalize: mean/var -> scale = gamma*rsqrt(var+eps), shift = beta - mean*scale
__global__ void k_stats_fin(int nparts, int ch, float cnt,
                            const float* __restrict__ gamma, const float* __restrict__ beta,
                            float* __restrict__ scale, float* __restrict__ shift) {
    int c = threadIdx.x;
    if (c >= ch) return;
    double s = 0.0, q = 0.0;
    for (int p = 0; p < nparts; p++) {
        s += (double)d_psum[p*ch + c];
        q += (double)d_psq [p*ch + c];
    }
    double mean = s / (double)cnt;
    double var = q / (double)cnt - mean*mean;
    float sc = gamma[c] * rsqrtf((float)var + 1e-5f);
    scale[c] = sc;
    shift[c] = beta[c] - (float)mean * sc;
}

// ---------------- three-body pass 1: channel sum/sumsq over 194,560 combos ----------------
// grid 640 blocks x 256 threads; block handles 16 (b,a,n) triples
__global__ void k_pass1(const int* __restrict__ nbr_idx) {
    int c = threadIdx.x;
    float s = 0.f, q = 0.f;
    for (int i = 0; i < 16; i++) {
        int r = blockIdx.x*16 + i;
        int n = r % NBR;
        int ba = r / NBR;           // b*AT + a
        int b = ba / AT;
        int j = nbr_idx[r];
        float base = d_PN[ba*768 + c] + d_PN[(b*AT + j)*768 + 256 + c] + d_QE[r*512 + c];
        int jrow = (b*AT + j)*NBR;
        #pragma unroll
        for (int k = 0; k < NK; k++) {
            int m = k + (k >= n);
            int vk = nbr_idx[jrow + m];
            float v = base + d_PN[(b*AT + vk)*768 + 512 + c] + d_QE[(jrow + m)*512 + 256 + c];
            s += v; q = fmaf(v, v, q);
        }
    }
    d_psum[blockIdx.x*256 + c] = s;
    d_psq [blockIdx.x*256 + c] = q;
}

// ---------------- three-body pass 2: BN + sigmoid*tanh + sum over k ----------------
// grid R2 blocks x 128 threads; thread t owns channel pair (t, t+128)
__global__ void __launch_bounds__(128) k_pass2(const int* __restrict__ nbr_idx) {
    int t = threadIdx.x;
    int r = blockIdx.x;
    int n = r % NBR;
    int ba = r / NBR;
    int b = ba / AT;
    int j = nbr_idx[r];
    float sg = d_scale3[t],     hg = d_shift3[t];
    float se = d_scale3[t+128], he = d_shift3[t+128];
    const float* PNa = d_PN + ba*768;
    const float* PNj = d_PN + (b*AT + j)*768;
    const float* QEr = d_QE + r*512;
    float baseg = PNa[t]     + PNj[256+t] + QEr[t];
    float basee = PNa[128+t] + PNj[384+t] + QEr[128+t];
    int jrow = (b*AT + j)*NBR;
    float acc = 0.f;
    #pragma unroll
    for (int k = 0; k < NK; k++) {
        int m = k + (k >= n);
        int vk = nbr_idx[jrow + m];
        const float* PNk = d_PN + (b*AT + vk)*768;
        const float* QEk = d_QE + (jrow + m)*512;
        float g = baseg + PNk[512+t] + QEk[256+t];
        float e = basee + PNk[640+t] + QEk[384+t];
        acc += sigmoidf_(fmaf(sg, g, hg)) * tanhf(fmaf(se, e, he));
    }
    d_TB[r*128 + t] = acc;
}

// ---------------- final: out = tanh(edge + two_body + BN(three_body)) ----------------
__global__ void k_out(const float* __restrict__ edge, float* __restrict__ out) {
    int idx = blockIdx.x*256 + threadIdx.x;
    if (idx >= R2*128) return;
    int c = idx & 127, r = idx >> 7;
    float g = fmaf(d_scale2[c],     d_Y2[r*256 + c],     d_shift2[c]);
    float e = fmaf(d_scale2[c+128], d_Y2[r*256 + c+128], d_shift2[c+128]);
    float two = sigmoidf_(g) * tanhf(e);
    float tb = fmaf(d_scaleS[c], d_TB[idx], d_shiftS[c]);
    out[idx] = tanhf(edge[idx] + two + tb);
}

// ---------------- launch ----------------
extern "C" void kernel_launch(void* const* d_in, const int* in_sizes, int n_in,
                              void* d_out, int out_size) {
    const float* node     = (const float*)d_in[0];
    const float* edge     = (const float*)d_in[1];
    const int*   nbr_idx  = (const int*)  d_in[2];
    const int*   nbr_mask = (const int*)  d_in[3];
    const float* W2       = (const float*)d_in[4];
    // d_in[5] = b2 (cancelled by BN)
    const float* W3       = (const float*)d_in[6];
    // d_in[7] = b3 (cancelled by BN)
    const float* g2  = (const float*)d_in[8];
    const float* be2 = (const float*)d_in[9];
    const float* g3  = (const float*)d_in[10];
    const float* be3 = (const float*)d_in[11];
    const float* gs  = (const float*)d_in[12];
    const float* bes = (const float*)d_in[13];
    float* out = (float*)d_out;

    float *p_C2, *p_Y2, *p_PN, *p_QE, *p_TB;
    float *p_sc2, *p_sh2, *p_sc3, *p_sh3, *p_scS, *p_shS;
    cudaGetSymbolAddress((void**)&p_C2,  d_C2);
    cudaGetSymbolAddress((void**)&p_Y2,  d_Y2);
    cudaGetSymbolAddress((void**)&p_PN,  d_PN);
    cudaGetSymbolAddress((void**)&p_QE,  d_QE);
    cudaGetSymbolAddress((void**)&p_TB,  d_TB);
    cudaGetSymbolAddress((void**)&p_sc2, d_scale2);
    cudaGetSymbolAddress((void**)&p_sh2, d_shift2);
    cudaGetSymbolAddress((void**)&p_sc3, d_scale3);
    cudaGetSymbolAddress((void**)&p_sh3, d_shift3);
    cudaGetSymbolAddress((void**)&p_scS, d_scaleS);
    cudaGetSymbolAddress((void**)&p_shS, d_shiftS);

    // c2 products
    k_c2<<<(R2*128 + 255)/256, 256>>>(node, nbr_idx, nbr_mask);

    // PN = node @ [W3a|W3b|W3c]   (512 x 768)
    for (int s = 0; s < 3; s++)
        gemm_k128<<<dim3(256/64, NODES/64), 256>>>(node, W3 + s*128*256, p_PN + s*256, 256, 768);
    // QE = edge @ [W3d|W3e]       (10240 x 512)
    for (int s = 0; s < 2; s++)
        gemm_k128<<<dim3(256/64, R2/64), 256>>>(edge, W3 + (3+s)*128*256, p_QE + s*256, 256, 512);
    // Y2 = C2 @ W2                (10240 x 256)
    gemm_k128<<<dim3(256/64, R2/64), 256>>>(p_C2, W2, p_Y2, 256, 256);

    // BN2 stats
    k_stats_part256<<<80, 256>>>(p_Y2, R2/80);
    k_stats_fin<<<1, 256>>>(80, 256, (float)R2, g2, be2, p_sc2, p_sh2);

    // three-body pass 1 (BN3 stats over 194,560 combos)
    k_pass1<<<R2/16, 256>>>(nbr_idx);
    k_stats_fin<<<1, 256>>>(R2/16, 256, (float)CNT3, g3, be3, p_sc3, p_sh3);

    // three-body pass 2 (BN3 apply + activation + k-sum)
    k_pass2<<<R2, 128>>>(nbr_idx);

    // final BN stats over three_body sums
    k_stats_part128<<<80, 128>>>(p_TB, R2/80);
    k_stats_fin<<<1, 128>>>(80, 128, (float)R2, gs, bes, p_scS, p_shS);

    // output (fuses two_body activation + final BN + tanh)
    k_out<<<(R2*128 + 255)/256, 256>>>(edge, out);
}

// round 2
// speedup vs baseline: 1.2682x; 1.2682x over previous
#include <cuda_runtime.h>
#include <math.h>

#define Bsz 4
#define AT 128
#define NBR 20
#define NK 19
#define R2 (Bsz*AT*NBR)        // 10240 edge rows
#define NODES (Bsz*AT)         // 512
#define CNT3 (R2*NK)           // 194560 three-body rows

// ---------------- scratch (static device globals; no allocation) ----------------
__device__ float d_Y2[R2*256];        // two-body pre-BN GEMM output
__device__ float d_PN[NODES*768];     // node @ [W3a|W3b|W3c]
__device__ float d_QE[R2*512];        // edge @ [W3d|W3e]
__device__ float d_TB[R2*128];        // three-body pre-final-BN sums
__device__ float d_psum[256*256 + 640*256];
__device__ float d_psq [256*256 + 640*256];
__device__ float d_scale2[256], d_shift2[256];
__device__ float d_scale3[256], d_shift3[256];
__device__ float d_scaleS[128], d_shiftS[128];

__device__ __forceinline__ float sigmoidf_(float x) { return 1.f/(1.f + __expf(-x)); }

// ---------------- one fused GEMM launch for PN, QE, Y2 ----------------
// grid (12, 168):
//   yt < 160, xt < 8 : QE tile  (A = edge,  B = W3 slice 3+(n0>>8), C = d_QE  ldc=512)
//   yt < 160, xt >= 8: Y2 tile  (A = c2 computed on the fly, B = W2, C = d_Y2 ldc=256)
//   yt >= 160        : PN tile  (A = node, B = W3 slice n0>>8,      C = d_PN  ldc=768)
__global__ void __launch_bounds__(256) gemm_all(
    const float* __restrict__ node, const float* __restrict__ edge,
    const int* __restrict__ nbr_idx, const int* __restrict__ nbr_mask,
    const float* __restrict__ W2, const float* __restrict__ W3) {
    __shared__ float Ast[64][65];   // transposed: Ast[k][m]
    __shared__ float Bs[64][64];
    __shared__ int   sRI[64];
    __shared__ int   sRJ[64];
    __shared__ float sM[64];
    int tid = threadIdx.x;
    int txx = tid & 15, tym = tid >> 4;
    int xt = blockIdx.x, yt = blockIdx.y;

    const float* A; const float* Bp; float* C;
    int ldc, cbase, m0, n0, mode;
    if (yt >= 160) {                       // PN
        mode = 2; m0 = (yt - 160)*64; n0 = xt*64;
        A = node; Bp = W3 + (n0 >> 8)*(128*256); cbase = n0 & 255;
        C = d_PN; ldc = 768;
    } else if (xt < 8) {                   // QE
        mode = 0; m0 = yt*64; n0 = xt*64;
        A = edge; Bp = W3 + (3 + (n0 >> 8))*(128*256); cbase = n0 & 255;
        C = d_QE; ldc = 512;
    } else {                               // Y2 (c2 fused)
        mode = 1; m0 = yt*64; n0 = (xt - 8)*64;
        A = node; Bp = W2; cbase = n0;
        C = d_Y2; ldc = 256;
        if (tid < 64) {
            int r = m0 + tid;
            int j = nbr_idx[r];
            int b = r / (AT*NBR);
            sRI[tid] = (r / NBR)*128;
            sRJ[tid] = (b*AT + j)*128;
            sM[tid]  = (float)nbr_mask[r];
        }
        __syncthreads();
    }

    float acc[4][4] = {};
    for (int k0 = 0; k0 < 128; k0 += 64) {
        if (mode == 1) {
            #pragma unroll
            for (int l = 0; l < 16; l++) {
                int e = l*256 + tid;
                int m = e >> 6, k = e & 63;
                Ast[k][m] = node[sRI[m] + k0 + k] * node[sRJ[m] + k0 + k] * sM[m];
            }
        } else {
            #pragma unroll
            for (int l = 0; l < 16; l++) {
                int e = l*256 + tid;
                int m = e >> 6, k = e & 63;
                Ast[k][m] = A[(m0 + m)*128 + k0 + k];
            }
        }
        #pragma unroll
        for (int l = 0; l < 16; l++) {
            int e = l*256 + tid;
            int k = e >> 6, n = e & 63;
            Bs[k][n] = Bp[(k0 + k)*256 + cbase + n];
        }
        __syncthreads();
        #pragma unroll 8
        for (int kk = 0; kk < 64; kk++) {
            float a0 = Ast[kk][tym*4+0];
            float a1 = Ast[kk][tym*4+1];
            float a2 = Ast[kk][tym*4+2];
            float a3 = Ast[kk][tym*4+3];
            float4 bv = *(const float4*)&Bs[kk][txx*4];
            acc[0][0] = fmaf(a0, bv.x, acc[0][0]); acc[0][1] = fmaf(a0, bv.y, acc[0][1]);
            acc[0][2] = fmaf(a0, bv.z, acc[0][2]); acc[0][3] = fmaf(a0, bv.w, acc[0][3]);
            acc[1][0] = fmaf(a1, bv.x, acc[1][0]); acc[1][1] = fmaf(a1, bv.y, acc[1][1]);
            acc[1][2] = fmaf(a1, bv.z, acc[1][2]); acc[1][3] = fmaf(a1, bv.w, acc[1][3]);
            acc[2][0] = fmaf(a2, bv.x, acc[2][0]); acc[2][1] = fmaf(a2, bv.y, acc[2][1]);
            acc[2][2] = fmaf(a2, bv.z, acc[2][2]); acc[2][3] = fmaf(a2, bv.w, acc[2][3]);
            acc[3][0] = fmaf(a3, bv.x, acc[3][0]); acc[3][1] = fmaf(a3, bv.y, acc[3][1]);
            acc[3][2] = fmaf(a3, bv.z, acc[3][2]); acc[3][3] = fmaf(a3, bv.w, acc[3][3]);
        }
        __syncthreads();
    }
    #pragma unroll
    for (int i = 0; i < 4; i++)
        #pragma unroll
        for (int jj = 0; jj < 4; jj++)
            C[(m0 + tym*4 + i)*ldc + n0 + txx*4 + jj] = acc[i][jj];
}

// ---------------- BN2 stat partials over Y2 (256 blocks x 40 rows) ----------------
__global__ void k_stats_part256(const float* __restrict__ X) {
    int c = threadIdx.x;
    float s = 0.f, q = 0.f;
    int r0 = blockIdx.x * 40;
    #pragma unroll 4
    for (int i = 0; i < 40; i++) {
        float v = X[(r0+i)*256 + c];
        s += v; q = fmaf(v, v, q);
    }
    d_psum[blockIdx.x*256 + c] = s;
    d_psq [blockIdx.x*256 + c] = q;
}

// ---------------- final BN stat partials over TB (160 blocks x 64 rows) ----------------
__global__ void k_stats_part128(const float* __restrict__ X) {
    int c = threadIdx.x;
    float s = 0.f, q = 0.f;
    int r0 = blockIdx.x * 64;
    #pragma unroll 4
    for (int i = 0; i < 64; i++) {
        float v = X[(r0+i)*128 + c];
        s += v; q = fmaf(v, v, q);
    }
    d_psum[blockIdx.x*128 + c] = s;
    d_psq [blockIdx.x*128 + c] = q;
}

// finalize body: scale = gamma*rsqrt(var+eps), shift = beta - mean*scale
__device__ __forceinline__ void fin_body(int c, int ch, int parts, int off, float cnt,
                                         const float* __restrict__ gamma,
                                         const float* __restrict__ beta,
                                         float* scale, float* shift) {
    const float* ps = d_psum + off;
    const float* pq = d_psq  + off;
    float s0=0.f,s1=0.f,s2=0.f,s3=0.f, q0=0.f,q1=0.f,q2=0.f,q3=0.f;
    int p = 0;
    for (; p + 4 <= parts; p += 4) {
        s0 += ps[(p+0)*ch + c]; q0 += pq[(p+0)*ch + c];
        s1 += ps[(p+1)*ch + c]; q1 += pq[(p+1)*ch + c];
        s2 += ps[(p+2)*ch + c]; q2 += pq[(p+2)*ch + c];
        s3 += ps[(p+3)*ch + c]; q3 += pq[(p+3)*ch + c];
    }
    for (; p < parts; p++) { s0 += ps[p*ch + c]; q0 += pq[p*ch + c]; }
    float s = (s0+s1) + (s2+s3);
    float q = (q0+q1) + (q2+q3);
    float mean = s / cnt;
    float var  = q / cnt - mean*mean;
    float sc = gamma[c] * rsqrtf(var + 1e-5f);
    scale[c] = sc;
    shift[c] = beta[c] - mean * sc;
}

// merged finalize for BN2 (block 0) and BN3 (block 1)
__global__ void k_fin23(const float* __restrict__ g2, const float* __restrict__ be2,
                        const float* __restrict__ g3, const float* __restrict__ be3) {
    int c = threadIdx.x;
    if (blockIdx.x == 0)
        fin_body(c, 256, 256, 0,        (float)R2,   g2, be2, d_scale2, d_shift2);
    else
        fin_body(c, 256, 640, 256*256,  (float)CNT3, g3, be3, d_scale3, d_shift3);
}

__global__ void k_finS(const float* __restrict__ gs, const float* __restrict__ bes) {
    fin_body(threadIdx.x, 128, 160, 0, (float)R2, gs, bes, d_scaleS, d_shiftS);
}

// ---------------- three-body pass 1: channel sum/sumsq over 194,560 combos ----------------
// grid 640 blocks x 256 threads; block handles 16 (b,a,n) edge rows
__global__ void k_pass1(const int* __restrict__ nbr_idx) {
    int c = threadIdx.x;
    float s = 0.f, q = 0.f;
    for (int i = 0; i < 16; i++) {
        int r = blockIdx.x*16 + i;
        int n = r % NBR;
        int ba = r / NBR;           // b*AT + a
        int b = ba / AT;
        int j = nbr_idx[r];
        float base = d_PN[ba*768 + c] + d_PN[(b*AT + j)*768 + 256 + c] + d_QE[r*512 + c];
        int jrow = (b*AT + j)*NBR;
        #pragma unroll
        for (int k = 0; k < NK; k++) {
            int m = k + (k >= n);
            int vk = nbr_idx[jrow + m];
            float v = base + d_PN[(b*AT + vk)*768 + 512 + c] + d_QE[(jrow + m)*512 + 256 + c];
            s += v; q = fmaf(v, v, q);
        }
    }
    d_psum[256*256 + blockIdx.x*256 + c] = s;
    d_psq [256*256 + blockIdx.x*256 + c] = q;
}

// ---------------- three-body pass 2: BN + sigmoid*tanh + sum over k ----------------
// grid R2 blocks x 128 threads; thread t owns channel pair (t, t+128)
__global__ void __launch_bounds__(128) k_pass2(const int* __restrict__ nbr_idx) {
    int t = threadIdx.x;
    int r = blockIdx.x;
    int n = r % NBR;
    int ba = r / NBR;
    int b = ba / AT;
    int j = nbr_idx[r];
    float sg = d_scale3[t],     hg = d_shift3[t];
    float se = d_scale3[t+128], he = d_shift3[t+128];
    const float* PNa = d_PN + ba*768;
    const float* PNj = d_PN + (b*AT + j)*768;
    const float* QEr = d_QE + r*512;
    float baseg = PNa[t]     + PNj[256+t] + QEr[t];
    float basee = PNa[128+t] + PNj[384+t] + QEr[128+t];
    int jrow = (b*AT + j)*NBR;
    float acc = 0.f;
    #pragma unroll
    for (int k = 0; k < NK; k++) {
        int m = k + (k >= n);
        int vk = nbr_idx[jrow + m];
        const float* PNk = d_PN + (b*AT + vk)*768;
        const float* QEk = d_QE + (jrow + m)*512;
        float g = baseg + PNk[512+t] + QEk[256+t];
        float e = basee + PNk[640+t] + QEk[384+t];
        acc += sigmoidf_(fmaf(sg, g, hg)) * tanhf(fmaf(se, e, he));
    }
    d_TB[r*128 + t] = acc;
}

// ---------------- final: out = tanh(edge + two_body + BN(three_body)) ----------------
__global__ void k_out(const float* __restrict__ edge, float* __restrict__ out) {
    int idx = blockIdx.x*256 + threadIdx.x;
    if (idx >= R2*128) return;
    int c = idx & 127, r = idx >> 7;
    float g = fmaf(d_scale2[c],     d_Y2[r*256 + c],     d_shift2[c]);
    float e = fmaf(d_scale2[c+128], d_Y2[r*256 + c+128], d_shift2[c+128]);
    float two = sigmoidf_(g) * tanhf(e);
    float tb = fmaf(d_scaleS[c], d_TB[idx], d_shiftS[c]);
    out[idx] = tanhf(edge[idx] + two + tb);
}

// ---------------- launch ----------------
extern "C" void kernel_launch(void* const* d_in, const int* in_sizes, int n_in,
                              void* d_out, int out_size) {
    const float* node     = (const float*)d_in[0];
    const float* edge     = (const float*)d_in[1];
    const int*   nbr_idx  = (const int*)  d_in[2];
    const int*   nbr_mask = (const int*)  d_in[3];
    const float* W2       = (const float*)d_in[4];
    // d_in[5] = b2 (cancelled by BN)
    const float* W3       = (const float*)d_in[6];
    // d_in[7] = b3 (cancelled by BN)
    const float* g2  = (const float*)d_in[8];
    const float* be2 = (const float*)d_in[9];
    const float* g3  = (const float*)d_in[10];
    const float* be3 = (const float*)d_in[11];
    const float* gs  = (const float*)d_in[12];
    const float* bes = (const float*)d_in[13];
    float* out = (float*)d_out;

    float *p_Y2, *p_TB;
    cudaGetSymbolAddress((void**)&p_Y2, d_Y2);
    cudaGetSymbolAddress((void**)&p_TB, d_TB);

    // 1. all GEMMs (PN, QE, Y2-with-fused-c2) in one launch
    gemm_all<<<dim3(12, 168), 256>>>(node, edge, nbr_idx, nbr_mask, W2, W3);

    // 2. BN2 stat partials over Y2
    k_stats_part256<<<256, 256>>>(p_Y2);

    // 3. three-body pass 1 (BN3 stat partials over 194,560 combos)
    k_pass1<<<640, 256>>>(nbr_idx);

    // 4. finalize BN2 + BN3 together
    k_fin23<<<2, 256>>>(g2, be2, g3, be3);

    // 5. three-body pass 2 (BN3 apply + activation + k-sum)
    k_pass2<<<R2, 128>>>(nbr_idx);

    // 6. final BN stat partials over three_body sums
    k_stats_part128<<<160, 128>>>(p_TB);

    // 7. finalize final BN
    k_finS<<<1, 128>>>(gs, bes);

    // 8. output (fuses two_body activation + final BN + tanh)
    k_out<<<(R2*128 + 255)/256, 256>>>(edge, out);
}

// round 3
// speedup vs baseline: 1.4588x; 1.1503x over previous
#include <cuda_runtime.h>
#include <math.h>

#define Bsz 4
#define AT 128
#define NBR 20
#define NK 19
#define R2 (Bsz*AT*NBR)        // 10240 edge rows
#define NODES (Bsz*AT)         // 512
#define CNT3 (R2*NK)           // 194560 three-body rows
#define OFF3 (256*256)         // BN3 partial offset in d_psum/d_psq

// ---------------- scratch (static device globals; no allocation) ----------------
__device__ float d_Y2[R2*256];        // two-body pre-BN GEMM output
__device__ float d_PN[NODES*768];     // node @ [W3a|W3b|W3c]
__device__ float d_QE[R2*512];        // edge @ [W3d|W3e]
__device__ float d_TB[R2*128];        // three-body pre-final-BN sums
__device__ float d_psum[OFF3 + 640*256];
__device__ float d_psq [OFF3 + 640*256];
__device__ float d_scale2[256], d_shift2[256];
__device__ float d_scale3[256], d_shift3[256];
__device__ float d_scaleS[128], d_shiftS[128];

__device__ __forceinline__ float sigmoidf_(float x) { return 1.f/(1.f + __expf(-x)); }

// ---------------- one fused GEMM launch for PN, QE, Y2 ----------------
// grid (12, 168):
//   yt < 160, xt < 8 : QE tile  (A = edge,  B = W3 slice 3+(n0>>8), C = d_QE  ldc=512)
//   yt < 160, xt >= 8: Y2 tile  (A = c2 on the fly, B = W2, C = d_Y2 ldc=256; BN2 stats fused)
//   yt >= 160        : PN tile  (A = node, B = W3 slice n0>>8,      C = d_PN  ldc=768)
__global__ void __launch_bounds__(256) gemm_all(
    const float* __restrict__ node, const float* __restrict__ edge,
    const int* __restrict__ nbr_idx, const int* __restrict__ nbr_mask,
    const float* __restrict__ W2, const float* __restrict__ W3) {
    __shared__ float Ast[64][65];   // transposed: Ast[k][m]
    __shared__ float Bs[64][64];
    __shared__ int   sRI[64];
    __shared__ int   sRJ[64];
    __shared__ float sM[64];
    int tid = threadIdx.x;
    int txx = tid & 15, tym = tid >> 4;
    int xt = blockIdx.x, yt = blockIdx.y;

    const float* A; const float* Bp; float* C;
    int ldc, cbase, m0, n0, mode;
    if (yt >= 160) {                       // PN
        mode = 2; m0 = (yt - 160)*64; n0 = xt*64;
        A = node; Bp = W3 + (n0 >> 8)*(128*256); cbase = n0 & 255;
        C = d_PN; ldc = 768;
    } else if (xt < 8) {                   // QE
        mode = 0; m0 = yt*64; n0 = xt*64;
        A = edge; Bp = W3 + (3 + (n0 >> 8))*(128*256); cbase = n0 & 255;
        C = d_QE; ldc = 512;
    } else {                               // Y2 (c2 fused)
        mode = 1; m0 = yt*64; n0 = (xt - 8)*64;
        A = node; Bp = W2; cbase = n0;
        C = d_Y2; ldc = 256;
        if (tid < 64) {
            int r = m0 + tid;
            int j = nbr_idx[r];
            int b = r / (AT*NBR);
            sRI[tid] = (r / NBR)*128;
            sRJ[tid] = (b*AT + j)*128;
            sM[tid]  = (float)nbr_mask[r];
        }
        __syncthreads();
    }

    float acc[4][4] = {};
    for (int k0 = 0; k0 < 128; k0 += 64) {
        if (mode == 1) {
            #pragma unroll
            for (int l = 0; l < 16; l++) {
                int e = l*256 + tid;
                int m = e >> 6, k = e & 63;
                Ast[k][m] = node[sRI[m] + k0 + k] * node[sRJ[m] + k0 + k] * sM[m];
            }
        } else {
            #pragma unroll
            for (int l = 0; l < 16; l++) {
                int e = l*256 + tid;
                int m = e >> 6, k = e & 63;
                Ast[k][m] = A[(m0 + m)*128 + k0 + k];
            }
        }
        #pragma unroll
        for (int l = 0; l < 16; l++) {
            int e = l*256 + tid;
            int k = e >> 6, n = e & 63;
            Bs[k][n] = Bp[(k0 + k)*256 + cbase + n];
        }
        __syncthreads();
        #pragma unroll 8
        for (int kk = 0; kk < 64; kk++) {
            float a0 = Ast[kk][tym*4+0];
            float a1 = Ast[kk][tym*4+1];
            float a2 = Ast[kk][tym*4+2];
            float a3 = Ast[kk][tym*4+3];
            float4 bv = *(const float4*)&Bs[kk][txx*4];
            acc[0][0] = fmaf(a0, bv.x, acc[0][0]); acc[0][1] = fmaf(a0, bv.y, acc[0][1]);
            acc[0][2] = fmaf(a0, bv.z, acc[0][2]); acc[0][3] = fmaf(a0, bv.w, acc[0][3]);
            acc[1][0] = fmaf(a1, bv.x, acc[1][0]); acc[1][1] = fmaf(a1, bv.y, acc[1][1]);
            acc[1][2] = fmaf(a1, bv.z, acc[1][2]); acc[1][3] = fmaf(a1, bv.w, acc[1][3]);
            acc[2][0] = fmaf(a2, bv.x, acc[2][0]); acc[2][1] = fmaf(a2, bv.y, acc[2][1]);
            acc[2][2] = fmaf(a2, bv.z, acc[2][2]); acc[2][3] = fmaf(a2, bv.w, acc[2][3]);
            acc[3][0] = fmaf(a3, bv.x, acc[3][0]); acc[3][1] = fmaf(a3, bv.y, acc[3][1]);
            acc[3][2] = fmaf(a3, bv.z, acc[3][2]); acc[3][3] = fmaf(a3, bv.w, acc[3][3]);
        }
        __syncthreads();
    }
    #pragma unroll
    for (int i = 0; i < 4; i++)
        #pragma unroll
        for (int jj = 0; jj < 4; jj++)
            C[(m0 + tym*4 + i)*ldc + n0 + txx*4 + jj] = acc[i][jj];

    // fused BN2 tile stats (Y2 tiles only): reduce acc over the 64 rows
    if (mode == 1) {
        #pragma unroll
        for (int jj = 0; jj < 4; jj++) {
            float s = 0.f, q = 0.f;
            #pragma unroll
            for (int i = 0; i < 4; i++) {
                float v = acc[i][jj];
                s += v; q = fmaf(v, v, q);
            }
            Ast[tym][txx*4+jj] = s;     // reuse smem: Ast = colsum, Bs = colsq
            Bs [tym][txx*4+jj] = q;
        }
        __syncthreads();
        if (tid < 64) {
            float s = 0.f, q = 0.f;
            #pragma unroll
            for (int t = 0; t < 16; t++) { s += Ast[t][tid]; q += Bs[t][tid]; }
            d_psum[yt*256 + n0 + tid] = s;
            d_psq [yt*256 + n0 + tid] = q;
        }
    }
}

// ---------------- warp-per-channel BN finalize ----------------
__device__ __forceinline__ void fin_warp(int lane, int c, int ch, int parts, int off, float cnt,
                                         const float* __restrict__ gamma,
                                         const float* __restrict__ beta,
                                         float* scale, float* shift) {
    const float* ps = d_psum + off;
    const float* pq = d_psq  + off;
    float s = 0.f, q = 0.f;
    for (int p = lane; p < parts; p += 32) {
        s += ps[p*ch + c];
        q += pq[p*ch + c];
    }
    #pragma unroll
    for (int o = 16; o; o >>= 1) {
        s += __shfl_xor_sync(0xffffffffu, s, o);
        q += __shfl_xor_sync(0xffffffffu, q, o);
    }
    if (lane == 0) {
        float mean = s / cnt;
        float var  = q / cnt - mean*mean;
        float sc = gamma[c] * rsqrtf(var + 1e-5f);
        scale[c] = sc;
        shift[c] = beta[c] - mean * sc;
    }
}

// grid 64 blocks x 256 threads (8 warps/block): warps 0..255 -> BN2 ch, 256..511 -> BN3 ch
__global__ void k_fin23(const float* __restrict__ g2, const float* __restrict__ be2,
                        const float* __restrict__ g3, const float* __restrict__ be3) {
    int w = blockIdx.x*8 + (threadIdx.x >> 5);
    int lane = threadIdx.x & 31;
    if (w < 256) fin_warp(lane, w,       256, 160, 0,    (float)R2,   g2, be2, d_scale2, d_shift2);
    else         fin_warp(lane, w - 256, 256, 640, OFF3, (float)CNT3, g3, be3, d_scale3, d_shift3);
}

// grid 16 blocks x 256 threads: 128 warps -> 128 channels
__global__ void k_finS(const float* __restrict__ gs, const float* __restrict__ bes) {
    int w = blockIdx.x*8 + (threadIdx.x >> 5);
    fin_warp(threadIdx.x & 31, w, 128, 160, 0, (float)R2, gs, bes, d_scaleS, d_shiftS);
}

// ---------------- final BN stat partials over TB (160 blocks x 64 rows) ----------------
__global__ void k_stats_part128(const float* __restrict__ X) {
    int c = threadIdx.x;
    float s = 0.f, q = 0.f;
    int r0 = blockIdx.x * 64;
    #pragma unroll 4
    for (int i = 0; i < 64; i++) {
        float v = X[(r0+i)*128 + c];
        s += v; q = fmaf(v, v, q);
    }
    d_psum[blockIdx.x*128 + c] = s;
    d_psq [blockIdx.x*128 + c] = q;
}

// ---------------- three-body pass 1: channel sum/sumsq over 194,560 combos ----------------
// grid 640 blocks x 256 threads; block handles 16 (b,a,n) edge rows
__global__ void k_pass1(const int* __restrict__ nbr_idx) {
    int c = threadIdx.x;
    float s = 0.f, q = 0.f;
    for (int i = 0; i < 16; i++) {
        int r = blockIdx.x*16 + i;
        int n = r % NBR;
        int ba = r / NBR;           // b*AT + a
        int b = ba / AT;
        int j = nbr_idx[r];
        float base = d_PN[ba*768 + c] + d_PN[(b*AT + j)*768 + 256 + c] + d_QE[r*512 + c];
        int jrow = (b*AT + j)*NBR;
        #pragma unroll
        for (int k = 0; k < NK; k++) {
            int m = k + (k >= n);
            int vk = nbr_idx[jrow + m];
            float v = base + d_PN[(b*AT + vk)*768 + 512 + c] + d_QE[(jrow + m)*512 + 256 + c];
            s += v; q = fmaf(v, v, q);
        }
    }
    d_psum[OFF3 + blockIdx.x*256 + c] = s;
    d_psq [OFF3 + blockIdx.x*256 + c] = q;
}

// ---------------- three-body pass 2: BN + sigmoid*tanh + sum over k ----------------
// grid R2 blocks x 128 threads; thread t owns channel pair (t, t+128)
__global__ void __launch_bounds__(128) k_pass2(const int* __restrict__ nbr_idx) {
    int t = threadIdx.x;
    int r = blockIdx.x;
    int n = r % NBR;
    int ba = r / NBR;
    int b = ba / AT;
    int j = nbr_idx[r];
    float sg = d_scale3[t],     hg = d_shift3[t];
    float se = d_scale3[t+128], he = d_shift3[t+128];
    const float* PNa = d_PN + ba*768;
    const float* PNj = d_PN + (b*AT + j)*768;
    const float* QEr = d_QE + r*512;
    float baseg = PNa[t]     + PNj[256+t] + QEr[t];
    float basee = PNa[128+t] + PNj[384+t] + QEr[128+t];
    int jrow = (b*AT + j)*NBR;
    float acc = 0.f;
    #pragma unroll
    for (int k = 0; k < NK; k++) {
        int m = k + (k >= n);
        int vk = nbr_idx[jrow + m];
        const float* PNk = d_PN + (b*AT + vk)*768;
        const float* QEk = d_QE + (jrow + m)*512;
        float g = baseg + PNk[512+t] + QEk[256+t];
        float e = basee + PNk[640+t] + QEk[384+t];
        acc += sigmoidf_(fmaf(sg, g, hg)) * tanhf(fmaf(se, e, he));
    }
    d_TB[r*128 + t] = acc;
}

// ---------------- final: out = tanh(edge + two_body + BN(three_body)) ----------------
__global__ void k_out(const float* __restrict__ edge, float* __restrict__ out) {
    int idx = blockIdx.x*256 + threadIdx.x;
    if (idx >= R2*128) return;
    int c = idx & 127, r = idx >> 7;
    float g = fmaf(d_scale2[c],     d_Y2[r*256 + c],     d_shift2[c]);
    float e = fmaf(d_scale2[c+128], d_Y2[r*256 + c+128], d_shift2[c+128]);
    float two = sigmoidf_(g) * tanhf(e);
    float tb = fmaf(d_scaleS[c], d_TB[idx], d_shiftS[c]);
    out[idx] = tanhf(edge[idx] + two + tb);
}

// ---------------- launch ----------------
extern "C" void kernel_launch(void* const* d_in, const int* in_sizes, int n_in,
                              void* d_out, int out_size) {
    const float* node     = (const float*)d_in[0];
    const float* edge     = (const float*)d_in[1];
    const int*   nbr_idx  = (const int*)  d_in[2];
    const int*   nbr_mask = (const int*)  d_in[3];
    const float* W2       = (const float*)d_in[4];
    // d_in[5] = b2 (cancelled by BN)
    const float* W3       = (const float*)d_in[6];
    // d_in[7] = b3 (cancelled by BN)
    const float* g2  = (const float*)d_in[8];
    const float* be2 = (const float*)d_in[9];
    const float* g3  = (const float*)d_in[10];
    const float* be3 = (const float*)d_in[11];
    const float* gs  = (const float*)d_in[12];
    const float* bes = (const float*)d_in[13];
    float* out = (float*)d_out;

    float *p_TB;
    cudaGetSymbolAddress((void**)&p_TB, d_TB);

    // 1. all GEMMs (PN, QE, Y2-with-fused-c2 + fused BN2 stats) in one launch
    gemm_all<<<dim3(12, 168), 256>>>(node, edge, nbr_idx, nbr_mask, W2, W3);

    // 2. three-body pass 1 (BN3 stat partials over 194,560 combos)
    k_pass1<<<640, 256>>>(nbr_idx);

    // 3. finalize BN2 + BN3 (warp per channel)
    k_fin23<<<64, 256>>>(g2, be2, g3, be3);

    // 4. three-body pass 2 (BN3 apply + activation + k-sum)
    k_pass2<<<R2, 128>>>(nbr_idx);

    // 5. final BN stat partials over three_body sums
    k_stats_part128<<<160, 128>>>(p_TB);

    // 6. finalize final BN (warp per channel)
    k_finS<<<16, 256>>>(gs, bes);

    // 7. output (fuses two_body activation + final BN + tanh)
    k_out<<<(R2*128 + 255)/256, 256>>>(edge, out);
}

// round 4
// speedup vs baseline: 2.2210x; 1.5225x over previous
#include <cuda_runtime.h>
#include <math.h>

#define Bsz 4
#define AT 128
#define NBR 20
#define NK 19
#define R2 (Bsz*AT*NBR)        // 10240 edge rows
#define NODES (Bsz*AT)         // 512
#define CNT3 (R2*NK)           // 194560 three-body rows
#define OFF3 (256*256)         // BN3 partial offset in d_psum/d_psq

// ---------------- scratch (static device globals; no allocation) ----------------
__device__ float d_Y2[R2*256];        // two-body pre-BN GEMM output
__device__ float d_PN[NODES*768];     // node @ [W3a|W3b|W3c]
__device__ float d_QE[R2*512];        // edge @ [W3d|W3e]
__device__ float d_TB[R2*128];        // three-body pre-final-BN sums
__device__ float d_S[NODES*256];      // per-node sum of w over its 20 neighbors
__device__ float d_Q[NODES*256];      // per-node sum of w^2
__device__ float d_psum[OFF3 + 640*256];
__device__ float d_psq [OFF3 + 640*256];
__device__ float d_scale2[256], d_shift2[256];
__device__ float d_scale3[256], d_shift3[256];
__device__ float d_scaleS[128], d_shiftS[128];

__device__ __forceinline__ float tanh_hw(float x) {
    float y; asm("tanh.approx.f32 %0, %1;" : "=f"(y) : "f"(x)); return y;
}
__device__ __forceinline__ float sigmoid_hw(float x) {
    return fmaf(tanh_hw(0.5f*x), 0.5f, 0.5f);
}
__device__ __forceinline__ float sigmoidf_(float x) { return 1.f/(1.f + __expf(-x)); }

// ---------------- one fused GEMM launch for PN, QE, Y2 ----------------
// grid (12, 168):
//   yt < 160, xt < 8 : QE tile  (A = edge,  B = W3 slice 3+(n0>>8), C = d_QE  ldc=512)
//   yt < 160, xt >= 8: Y2 tile  (A = c2 on the fly, B = W2, C = d_Y2 ldc=256; BN2 stats fused)
//   yt >= 160        : PN tile  (A = node, B = W3 slice n0>>8,      C = d_PN  ldc=768)
__global__ void __launch_bounds__(256) gemm_all(
    const float* __restrict__ node, const float* __restrict__ edge,
    const int* __restrict__ nbr_idx, const int* __restrict__ nbr_mask,
    const float* __restrict__ W2, const float* __restrict__ W3) {
    __shared__ float Ast[64][65];   // transposed: Ast[k][m]
    __shared__ float Bs[64][64];
    __shared__ int   sRI[64];
    __shared__ int   sRJ[64];
    __shared__ float sM[64];
    int tid = threadIdx.x;
    int txx = tid & 15, tym = tid >> 4;
    int xt = blockIdx.x, yt = blockIdx.y;

    const float* A; const float* Bp; float* C;
    int ldc, cbase, m0, n0, mode;
    if (yt >= 160) {                       // PN
        mode = 2; m0 = (yt - 160)*64; n0 = xt*64;
        A = node; Bp = W3 + (n0 >> 8)*(128*256); cbase = n0 & 255;
        C = d_PN; ldc = 768;
    } else if (xt < 8) {                   // QE
        mode = 0; m0 = yt*64; n0 = xt*64;
        A = edge; Bp = W3 + (3 + (n0 >> 8))*(128*256); cbase = n0 & 255;
        C = d_QE; ldc = 512;
    } else {                               // Y2 (c2 fused)
        mode = 1; m0 = yt*64; n0 = (xt - 8)*64;
        A = node; Bp = W2; cbase = n0;
        C = d_Y2; ldc = 256;
        if (tid < 64) {
            int r = m0 + tid;
            int j = nbr_idx[r];
            int b = r / (AT*NBR);
            sRI[tid] = (r / NBR)*128;
            sRJ[tid] = (b*AT + j)*128;
            sM[tid]  = (float)nbr_mask[r];
        }
        __syncthreads();
    }

    float acc[4][4] = {};
    for (int k0 = 0; k0 < 128; k0 += 64) {
        if (mode == 1) {
            #pragma unroll
            for (int l = 0; l < 16; l++) {
                int e = l*256 + tid;
                int m = e >> 6, k = e & 63;
                Ast[k][m] = node[sRI[m] + k0 + k] * node[sRJ[m] + k0 + k] * sM[m];
            }
        } else {
            #pragma unroll
            for (int l = 0; l < 16; l++) {
                int e = l*256 + tid;
                int m = e >> 6, k = e & 63;
                Ast[k][m] = A[(m0 + m)*128 + k0 + k];
            }
        }
        #pragma unroll
        for (int l = 0; l < 16; l++) {
            int e = l*256 + tid;
            int k = e >> 6, n = e & 63;
            Bs[k][n] = Bp[(k0 + k)*256 + cbase + n];
        }
        __syncthreads();
        #pragma unroll 8
        for (int kk = 0; kk < 64; kk++) {
            float a0 = Ast[kk][tym*4+0];
            float a1 = Ast[kk][tym*4+1];
            float a2 = Ast[kk][tym*4+2];
            float a3 = Ast[kk][tym*4+3];
            float4 bv = *(const float4*)&Bs[kk][txx*4];
            acc[0][0] = fmaf(a0, bv.x, acc[0][0]); acc[0][1] = fmaf(a0, bv.y, acc[0][1]);
            acc[0][2] = fmaf(a0, bv.z, acc[0][2]); acc[0][3] = fmaf(a0, bv.w, acc[0][3]);
            acc[1][0] = fmaf(a1, bv.x, acc[1][0]); acc[1][1] = fmaf(a1, bv.y, acc[1][1]);
            acc[1][2] = fmaf(a1, bv.z, acc[1][2]); acc[1][3] = fmaf(a1, bv.w, acc[1][3]);
            acc[2][0] = fmaf(a2, bv.x, acc[2][0]); acc[2][1] = fmaf(a2, bv.y, acc[2][1]);
            acc[2][2] = fmaf(a2, bv.z, acc[2][2]); acc[2][3] = fmaf(a2, bv.w, acc[2][3]);
            acc[3][0] = fmaf(a3, bv.x, acc[3][0]); acc[3][1] = fmaf(a3, bv.y, acc[3][1]);
            acc[3][2] = fmaf(a3, bv.z, acc[3][2]); acc[3][3] = fmaf(a3, bv.w, acc[3][3]);
        }
        __syncthreads();
    }
    #pragma unroll
    for (int i = 0; i < 4; i++)
        #pragma unroll
        for (int jj = 0; jj < 4; jj++)
            C[(m0 + tym*4 + i)*ldc + n0 + txx*4 + jj] = acc[i][jj];

    // fused BN2 tile stats (Y2 tiles only)
    if (mode == 1) {
        #pragma unroll
        for (int jj = 0; jj < 4; jj++) {
            float s = 0.f, q = 0.f;
            #pragma unroll
            for (int i = 0; i < 4; i++) {
                float v = acc[i][jj];
                s += v; q = fmaf(v, v, q);
            }
            Ast[tym][txx*4+jj] = s;
            Bs [tym][txx*4+jj] = q;
        }
        __syncthreads();
        if (tid < 64) {
            float s = 0.f, q = 0.f;
            #pragma unroll
            for (int t = 0; t < 16; t++) { s += Ast[t][tid]; q += Bs[t][tid]; }
            d_psum[yt*256 + n0 + tid] = s;
            d_psq [yt*256 + n0 + tid] = q;
        }
    }
}

// ---------------- per-node neighbor aggregate: S_j, Q_j over all 20 neighbors ----------------
// grid 512 blocks x 256 threads; w_{j,m}[c] = PN[vk_m][512+c] + QE[jrow+m][256+c]
__global__ void k_nodeagg(const int* __restrict__ nbr_idx) {
    int c = threadIdx.x;
    int bj = blockIdx.x;
    int b = bj >> 7;
    int jrow = bj * NBR;
    float s = 0.f, q = 0.f;
    #pragma unroll
    for (int m = 0; m < NBR; m++) {
        int vk = nbr_idx[jrow + m];
        float w = d_PN[(b*AT + vk)*768 + 512 + c] + d_QE[(jrow + m)*512 + 256 + c];
        s += w; q = fmaf(w, w, q);
    }
    d_S[bj*256 + c] = s;
    d_Q[bj*256 + c] = q;
}

// ---------------- three-body pass 1 (closed form): stats over 194,560 combos ----------------
// grid 640 blocks x 256 threads; block handles 16 edge rows, O(1) per row
__global__ void k_pass1(const int* __restrict__ nbr_idx) {
    int c = threadIdx.x;
    float s = 0.f, q = 0.f;
    for (int i = 0; i < 16; i++) {
        int r = blockIdx.x*16 + i;
        int n = r % NBR;
        int ba = r / NBR;
        int b = ba >> 7;
        int j = nbr_idx[r];
        int bj = b*AT + j;
        int jrow = bj*NBR;
        float base = d_PN[ba*768 + c] + d_PN[bj*768 + 256 + c] + d_QE[r*512 + c];
        int vkn = nbr_idx[jrow + n];
        float wn = d_PN[(b*AT + vkn)*768 + 512 + c] + d_QE[(jrow + n)*512 + 256 + c];
        float Sm = d_S[bj*256 + c] - wn;
        float Qm = d_Q[bj*256 + c] - wn*wn;
        s += fmaf((float)NK, base, Sm);
        q += fmaf((float)NK*base + 2.f*Sm, base, Qm);
    }
    d_psum[OFF3 + blockIdx.x*256 + c] = s;
    d_psq [OFF3 + blockIdx.x*256 + c] = q;
}

// ---------------- warp-per-channel BN finalize ----------------
__device__ __forceinline__ void fin_warp(int lane, int c, int ch, int parts, int off, float cnt,
                                         const float* __restrict__ gamma,
                                         const float* __restrict__ beta,
                                         float* scale, float* shift) {
    const float* ps = d_psum + off;
    const float* pq = d_psq  + off;
    float s = 0.f, q = 0.f;
    for (int p = lane; p < parts; p += 32) {
        s += ps[p*ch + c];
        q += pq[p*ch + c];
    }
    #pragma unroll
    for (int o = 16; o; o >>= 1) {
        s += __shfl_xor_sync(0xffffffffu, s, o);
        q += __shfl_xor_sync(0xffffffffu, q, o);
    }
    if (lane == 0) {
        float mean = s / cnt;
        float var  = q / cnt - mean*mean;
        float sc = gamma[c] * rsqrtf(var + 1e-5f);
        scale[c] = sc;
        shift[c] = beta[c] - mean * sc;
    }
}

// grid 64 blocks x 256 threads: warps 0..255 -> BN2 ch, 256..511 -> BN3 ch
__global__ void k_fin23(const float* __restrict__ g2, const float* __restrict__ be2,
                        const float* __restrict__ g3, const float* __restrict__ be3) {
    int w = blockIdx.x*8 + (threadIdx.x >> 5);
    int lane = threadIdx.x & 31;
    if (w < 256) fin_warp(lane, w,       256, 160, 0,    (float)R2,   g2, be2, d_scale2, d_shift2);
    else         fin_warp(lane, w - 256, 256, 640, OFF3, (float)CNT3, g3, be3, d_scale3, d_shift3);
}

// grid 16 blocks x 256 threads: 128 warps -> 128 channels
__global__ void k_finS(const float* __restrict__ gs, const float* __restrict__ bes) {
    int w = blockIdx.x*8 + (threadIdx.x >> 5);
    fin_warp(threadIdx.x & 31, w, 128, 160, 0, (float)R2, gs, bes, d_scaleS, d_shiftS);
}

// ---------------- final BN stat partials over TB (160 blocks x 64 rows) ----------------
__global__ void k_stats_part128(const float* __restrict__ X) {
    int c = threadIdx.x;
    float s = 0.f, q = 0.f;
    int r0 = blockIdx.x * 64;
    #pragma unroll 4
    for (int i = 0; i < 64; i++) {
        float v = X[(r0+i)*128 + c];
        s += v; q = fmaf(v, v, q);
    }
    d_psum[blockIdx.x*128 + c] = s;
    d_psq [blockIdx.x*128 + c] = q;
}

// ---------------- three-body pass 2: BN + sigmoid*tanh (HW approx) + sum over k ----------------
// grid R2 blocks x 128 threads; thread t owns channel pair (t, t+128)
__global__ void __launch_bounds__(128) k_pass2(const int* __restrict__ nbr_idx) {
    __shared__ int soPN[NK];    // PN row offsets for the 19 k's
    __shared__ int soQE[NK];    // QE row offsets
    int t = threadIdx.x;
    int r = blockIdx.x;
    int n = r % NBR;
    int ba = r / NBR;
    int b = ba >> 7;
    int j = nbr_idx[r];
    int jrow = (b*AT + j)*NBR;
    if (t < NK) {
        int m = t + (t >= n);
        int vk = nbr_idx[jrow + m];
        soPN[t] = (b*AT + vk)*768;
        soQE[t] = (jrow + m)*512;
    }
    float sg = d_scale3[t],     hg = d_shift3[t];
    float se = d_scale3[t+128], he = d_shift3[t+128];
    const float* PNa = d_PN + ba*768;
    const float* PNj = d_PN + (b*AT + j)*768;
    const float* QEr = d_QE + r*512;
    float baseg = fmaf(sg, PNa[t]     + PNj[256+t] + QEr[t],     hg);
    float basee = fmaf(se, PNa[128+t] + PNj[384+t] + QEr[128+t], he);
    __syncthreads();
    float acc = 0.f;
    #pragma unroll
    for (int k = 0; k < NK; k++) {
        const float* PNk = d_PN + soPN[k];
        const float* QEk = d_QE + soQE[k];
        float g = fmaf(sg, PNk[512+t] + QEk[256+t], baseg);
        float e = fmaf(se, PNk[640+t] + QEk[384+t], basee);
        acc += sigmoid_hw(g) * tanh_hw(e);
    }
    d_TB[r*128 + t] = acc;
}

// ---------------- final: out = tanh(edge + two_body + BN(three_body)) ----------------
__global__ void k_out(const float* __restrict__ edge, float* __restrict__ out) {
    int idx = blockIdx.x*256 + threadIdx.x;
    if (idx >= R2*128) return;
    int c = idx & 127, r = idx >> 7;
    float g = fmaf(d_scale2[c],     d_Y2[r*256 + c],     d_shift2[c]);
    float e = fmaf(d_scale2[c+128], d_Y2[r*256 + c+128], d_shift2[c+128]);
    float two = sigmoidf_(g) * tanhf(e);
    float tb = fmaf(d_scaleS[c], d_TB[idx], d_shiftS[c]);
    out[idx] = tanhf(edge[idx] + two + tb);
}

// ---------------- launch ----------------
extern "C" void kernel_launch(void* const* d_in, const int* in_sizes, int n_in,
                              void* d_out, int out_size) {
    const float* node     = (const float*)d_in[0];
    const float* edge     = (const float*)d_in[1];
    const int*   nbr_idx  = (const int*)  d_in[2];
    const int*   nbr_mask = (const int*)  d_in[3];
    const float* W2       = (const float*)d_in[4];
    const float* W3       = (const float*)d_in[6];
    const float* g2  = (const float*)d_in[8];
    const float* be2 = (const float*)d_in[9];
    const float* g3  = (const float*)d_in[10];
    const float* be3 = (const float*)d_in[11];
    const float* gs  = (const float*)d_in[12];
    const float* bes = (const float*)d_in[13];
    float* out = (float*)d_out;

    float *p_TB;
    cudaGetSymbolAddress((void**)&p_TB, d_TB);

    // 1. all GEMMs (PN, QE, Y2 + fused BN2 stats)
    gemm_all<<<dim3(12, 168), 256>>>(node, edge, nbr_idx, nbr_mask, W2, W3);

    // 2. per-node neighbor aggregates S_j, Q_j
    k_nodeagg<<<NODES, 256>>>(nbr_idx);

    // 3. three-body pass 1 (closed-form BN3 stats)
    k_pass1<<<640, 256>>>(nbr_idx);

    // 4. finalize BN2 + BN3
    k_fin23<<<64, 256>>>(g2, be2, g3, be3);

    // 5. three-body pass 2 (BN3 apply + HW activation + k-sum)
    k_pass2<<<R2, 128>>>(nbr_idx);

    // 6. final BN stat partials
    k_stats_part128<<<160, 128>>>(p_TB);

    // 7. finalize final BN
    k_finS<<<16, 256>>>(gs, bes);

    // 8. output
    k_out<<<(R2*128 + 255)/256, 256>>>(edge, out);
}